// round 5
// baseline (speedup 1.0000x reference)
#include <cuda_runtime.h>

// ---------------------------------------------------------------------------
// 2-layer LSTM (H=51), B=4096, T=1000 + 100 future steps.
// 147 blocks x 416 threads; NB=28 batch elements per block.
// lane = batch element; each warp owns 4 LSTM cells (4 gate rows each) for
// BOTH layers. Gate accumulators live in registers as f32x2 pairs (i,f),(g,o);
// cell states c1,c2 live in registers for the entire kernel. h1/h2/x are
// double-buffered in shared memory (parity = t&1) so GEMM reads buf p while
// cell updates write buf 1-p -> GEMM and cell update fuse into one phase.
// 2 __syncthreads per step (3 during the autoregressive tail).
//
// W layout: Wq[quad][k][16] = 4 cells x 4 gates (i,f,g,o) per k -> per cell a
// 16B uniform LDS.128 yields the two f32x2 weight pairs directly.
// ---------------------------------------------------------------------------

#define H       51
#define TSTEPS  1000
#define NTOT    1100
#define BATCH   4096
#define NB      28
#define NBLK    147
#define BPAD    (NBLK * NB)       // 4116
#define NTH     416               // 13 warps
#define NW      13
#define CPW     4                 // cells per warp (warp 12: cells 48..50 + pad)
#define NCELLQ  52                // 13*4 padded cells
#define K1      52                // GEMM1 k: rows 0..50 h1, row 51 x
#define KH      51                // GEMM2 sub-loop length
#define SROWS   105               // 0..50 h1, 51 x, 52 unused, 53..103 h2, 104 dummy
#define SSTR    32                // padded row stride (floats)

typedef unsigned long long ull;

__device__ float g_xT[TSTEPS * BPAD];   // transposed input [t][b]

struct Smem {
    float W1[NW * K1 * 16];       // [quad][k][cell*4+gate]
    float W2[NW * (2*KH) * 16];   // k 0..50: Wih2^T rows; 51..101: Whh2^T rows
    float Sbuf[2][SROWS][SSTR];
    float bias1[NCELLQ * 4];      // (bi,bf,bg,bo) per cell
    float bias2[NCELLQ * 4];
    float outp[NW][SSTR];         // per-warp partial output dots
};

__device__ __forceinline__ float sigf(float x) {
    return 1.0f / (1.0f + __expf(-x));
}
__device__ __forceinline__ float tanh_f(float x) {
    float e = __expf(-2.0f * fabsf(x));
    float t = (1.0f - e) / (1.0f + e);
    return copysignf(t, x);
}
__device__ __forceinline__ ull dup2(float w) {
    ull r; asm("mov.b64 %0, {%1, %1};" : "=l"(r) : "f"(w)); return r;
}
__device__ __forceinline__ void fma2(ull& d, ull a, ull b) {
    asm("fma.rn.f32x2 %0, %1, %2, %0;" : "+l"(d) : "l"(a), "l"(b));
}
__device__ __forceinline__ float2 unpk(ull v) {
    float2 f; asm("mov.b64 {%0, %1}, %2;" : "=f"(f.x), "=f"(f.y) : "l"(v)); return f;
}

__global__ void prep_kernel(const float* __restrict__ in) {
    int stride = gridDim.x * blockDim.x;
    for (int idx = blockIdx.x * blockDim.x + threadIdx.x;
         idx < BPAD * TSTEPS; idx += stride) {
        int b = idx / TSTEPS;
        int t = idx - b * TSTEPS;
        g_xT[t * BPAD + b] = (b < BATCH) ? in[idx] : 0.0f;
    }
}

// GEMM slab: acc over nk k-values using S rows [base..] of Sb and W entries
// Wk[k0..].  8 FFMA2 per k.
__device__ __forceinline__ void slab(ull a[8], const float* __restrict__ Wk,
                                     const float (*Sb)[SSTR], int base,
                                     int k0, int nk, int lane) {
    #pragma unroll 3
    for (int kk = 0; kk < nk; ++kk) {
        ull s2 = dup2(Sb[base + kk][lane]);
        const float* w = Wk + (k0 + kk) * 16;
        ulonglong2 w01 = *reinterpret_cast<const ulonglong2*>(w);
        ulonglong2 w23 = *reinterpret_cast<const ulonglong2*>(w + 4);
        ulonglong2 w45 = *reinterpret_cast<const ulonglong2*>(w + 8);
        ulonglong2 w67 = *reinterpret_cast<const ulonglong2*>(w + 12);
        fma2(a[0], w01.x, s2); fma2(a[1], w01.y, s2);
        fma2(a[2], w23.x, s2); fma2(a[3], w23.y, s2);
        fma2(a[4], w45.x, s2); fma2(a[5], w45.y, s2);
        fma2(a[6], w67.x, s2); fma2(a[7], w67.y, s2);
    }
}

__global__ __launch_bounds__(NTH, 1)
void lstm_kernel(const float* __restrict__ Wih1, const float* __restrict__ Whh1,
                 const float* __restrict__ bih1, const float* __restrict__ bhh1,
                 const float* __restrict__ Wih2, const float* __restrict__ Whh2,
                 const float* __restrict__ bih2, const float* __restrict__ bhh2,
                 const float* __restrict__ Wlin, const float* __restrict__ blin,
                 float* __restrict__ out) {
    extern __shared__ unsigned char smraw[];
    Smem* sm = reinterpret_cast<Smem*>(smraw);
    const int tid  = threadIdx.x;
    const int wid  = tid >> 5;
    const int lane = tid & 31;
    const int b0   = blockIdx.x * NB;
    const int c0   = wid * CPW;           // first cell of this warp

    // ---- one-time init ----
    // W1: [quad][k 0..51][cell*4+gate]; k<51 -> Whh1 col k, k==51 -> Wih1.
    for (int idx = tid; idx < NW * K1 * 16; idx += NTH) {
        int q = idx / (K1 * 16), rem = idx - q * (K1 * 16);
        int k = rem >> 4, j = rem & 15;
        int c = q * CPW + (j >> 2), g4 = j & 3;
        float v = 0.0f;
        if (c < H) {
            int row = g4 * H + c;
            v = (k < H) ? Whh1[row * H + k] : Wih1[row];
        }
        sm->W1[idx] = v;
    }
    // W2: k 0..50 -> Wih2 col k (against h1); k 51..101 -> Whh2 col k-51.
    for (int idx = tid; idx < NW * (2*KH) * 16; idx += NTH) {
        int q = idx / (2*KH * 16), rem = idx - q * (2*KH * 16);
        int k = rem >> 4, j = rem & 15;
        int c = q * CPW + (j >> 2), g4 = j & 3;
        float v = 0.0f;
        if (c < H) {
            int row = g4 * H + c;
            v = (k < H) ? Wih2[row * H + k] : Whh2[row * H + (k - H)];
        }
        sm->W2[idx] = v;
    }
    for (int idx = tid; idx < NCELLQ * 4; idx += NTH) {
        int c = idx >> 2, g4 = idx & 3;
        float v1 = 0.0f, v2 = 0.0f;
        if (c < H) {
            int row = g4 * H + c;
            v1 = bih1[row] + bhh1[row];
            v2 = bih2[row] + bhh2[row];
        }
        sm->bias1[idx] = v1;
        sm->bias2[idx] = v2;
    }
    for (int idx = tid; idx < 2 * SROWS * SSTR; idx += NTH)
        (&sm->Sbuf[0][0][0])[idx] = 0.0f;
    __syncthreads();
    // stage x(0) into Sbuf[0] (parity of t=0)
    if (tid < NB) sm->Sbuf[0][H][tid] = g_xT[b0 + tid];
    __syncthreads();

    // per-warp constants
    const float* Wk1 = sm->W1 + wid * (K1 * 16);
    const float* Wk2 = sm->W2 + wid * (2*KH * 16);
    float wl[CPW];
    #pragma unroll
    for (int j = 0; j < CPW; ++j)
        wl[j] = (c0 + j < H) ? Wlin[c0 + j] : 0.0f;
    const float blin_v = blin[0];
    // row indices for h writes (pad cell -> dummy row 104)
    int r1[CPW], r2[CPW];
    #pragma unroll
    for (int j = 0; j < CPW; ++j) {
        int c = c0 + j;
        r1[j] = (c < H) ? c : 104;
        r2[j] = (c < H) ? 53 + c : 104;
    }

    float c1r[CPW] = {0,0,0,0};
    float c2r[CPW] = {0,0,0,0};

    for (int t = 0; t < NTOT; ++t) {
        const int p = t & 1;
        const float (*Sp)[SSTR] = sm->Sbuf[p];       // prev-state buffer
        float (*Sn)[SSTR]       = sm->Sbuf[1 - p];   // next-state buffer

        // ================= P1: out-reduce / x-stage + GEMM1 + cell1 ========
        if (wid == 0 && lane < NB) {
            if (t > 0 && t < TSTEPS) {               // reduce out(t-1), store
                float acc = blin_v;
                #pragma unroll
                for (int w = 0; w < NW; ++w) acc += sm->outp[w][lane];
                int b = b0 + lane;
                if (b < BATCH) out[b * NTOT + (t - 1)] = acc;
            }
            if (t + 1 < TSTEPS)                      // stage x(t+1) -> Sn[51]
                Sn[H][lane] = g_xT[(t + 1) * BPAD + b0 + lane];
        }

        {   // GEMM1: k = 52 rows of Sp (h1(t-1) + x(t))
            ull a[8];
            #pragma unroll
            for (int j = 0; j < CPW; ++j) {
                ulonglong2 bq = *reinterpret_cast<const ulonglong2*>(
                                    &sm->bias1[(c0 + j) * 4]);
                a[2*j] = bq.x; a[2*j + 1] = bq.y;
            }
            slab(a, Wk1, Sp, 0, 0, K1, lane);
            // cell update layer 1 (registers only), write h1 -> Sn
            #pragma unroll
            for (int j = 0; j < CPW; ++j) {
                float2 if_ = unpk(a[2*j]);
                float2 go  = unpk(a[2*j + 1]);
                float cn = sigf(if_.y) * c1r[j] + sigf(if_.x) * tanh_f(go.x);
                float hn = sigf(go.y) * tanh_f(cn);
                c1r[j] = cn;
                if (lane < NB) Sn[r1[j]][lane] = hn;
            }
        }
        __syncthreads();

        // ================= P2: GEMM2 + cell2 + output partial ==============
        {
            ull a[8];
            #pragma unroll
            for (int j = 0; j < CPW; ++j) {
                ulonglong2 bq = *reinterpret_cast<const ulonglong2*>(
                                    &sm->bias2[(c0 + j) * 4]);
                a[2*j] = bq.x; a[2*j + 1] = bq.y;
            }
            slab(a, Wk2, Sn, 0,  0,  KH, lane);   // h1(t)   rows 0..50 of Sn
            slab(a, Wk2, Sp, 53, KH, KH, lane);   // h2(t-1) rows 53..103 of Sp
            float po = 0.0f;
            #pragma unroll
            for (int j = 0; j < CPW; ++j) {
                float2 if_ = unpk(a[2*j]);
                float2 go  = unpk(a[2*j + 1]);
                float cn = sigf(if_.y) * c2r[j] + sigf(if_.x) * tanh_f(go.x);
                float hn = sigf(go.y) * tanh_f(cn);
                c2r[j] = cn;
                if (lane < NB) Sn[r2[j]][lane] = hn;
                po += wl[j] * hn;
            }
            sm->outp[wid][lane] = po;
        }
        __syncthreads();

        // ================= P3 (future tail only): out -> x(t+1) ============
        if (t >= TSTEPS - 1) {
            if (wid == 0 && lane < NB) {
                float acc = blin_v;
                #pragma unroll
                for (int w = 0; w < NW; ++w) acc += sm->outp[w][lane];
                int b = b0 + lane;
                if (b < BATCH) out[b * NTOT + t] = acc;
                // x(t+1) must live in the buffer read as Sp at step t+1,
                // i.e. Sbuf[(t+1)&1] = Sbuf[1-p]  (this was the R4 bug)
                sm->Sbuf[1 - p][H][lane] = acc;
            }
            __syncthreads();
        }
    }
}

extern "C" void kernel_launch(void* const* d_in, const int* in_sizes, int n_in,
                              void* d_out, int out_size) {
    const float* inputs = (const float*)d_in[0];
    const float* Wih1   = (const float*)d_in[1];
    const float* Whh1   = (const float*)d_in[2];
    const float* bih1   = (const float*)d_in[3];
    const float* bhh1   = (const float*)d_in[4];
    const float* Wih2   = (const float*)d_in[5];
    const float* Whh2   = (const float*)d_in[6];
    const float* bih2   = (const float*)d_in[7];
    const float* bhh2   = (const float*)d_in[8];
    const float* Wlin   = (const float*)d_in[9];
    const float* blin   = (const float*)d_in[10];

    cudaFuncSetAttribute(lstm_kernel,
                         cudaFuncAttributeMaxDynamicSharedMemorySize,
                         (int)sizeof(Smem));

    prep_kernel<<<256, 256>>>(inputs);
    lstm_kernel<<<NBLK, NTH, sizeof(Smem)>>>(Wih1, Whh1, bih1, bhh1,
                                             Wih2, Whh2, bih2, bhh2,
                                             Wlin, blin, (float*)d_out);
}

// round 6
// speedup vs baseline: 1.0018x; 1.0018x over previous
#include <cuda_runtime.h>

// ---------------------------------------------------------------------------
// 2-layer LSTM (H=51), B=4096, T=1000 + 100 future steps.
// 147 blocks x 416 threads; NB=28 batch elements per block.
// lane = batch element; each warp owns 4 LSTM cells (4 gate rows each) for
// BOTH layers. Gate accumulators live in registers as f32x2 pairs (i,f),(g,o);
// cell states c1,c2 live in registers for the entire kernel. h1/h2/x are
// double-buffered in shared memory (parity = t&1) so GEMM reads buf p while
// cell updates write buf 1-p -> GEMM and cell update fuse into one phase.
// 2 __syncthreads per step (3 during the autoregressive tail).
//
// W layout: Wq[quad][k][16] = 4 cells x 4 gates (i,f,g,o) per k -> per cell a
// 16B uniform LDS.128 yields the two f32x2 weight pairs directly.
// ---------------------------------------------------------------------------

#define H       51
#define TSTEPS  1000
#define NTOT    1100
#define BATCH   4096
#define NB      28
#define NBLK    147
#define BPAD    (NBLK * NB)       // 4116
#define NTH     416               // 13 warps
#define NW      13
#define CPW     4                 // cells per warp (warp 12: cells 48..50 + pad)
#define NCELLQ  52                // 13*4 padded cells
#define K1      52                // GEMM1 k: rows 0..50 h1, row 51 x
#define KH      51                // GEMM2 sub-loop length
#define SROWS   105               // 0..50 h1, 51 x, 52 unused, 53..103 h2, 104 dummy
#define SSTR    32                // padded row stride (floats)

typedef unsigned long long ull;

__device__ float g_xT[TSTEPS * BPAD];   // transposed input [t][b]

struct Smem {
    float W1[NW * K1 * 16];       // [quad][k][cell*4+gate]
    float W2[NW * (2*KH) * 16];   // k 0..50: Wih2^T rows; 51..101: Whh2^T rows
    float Sbuf[2][SROWS][SSTR];
    float bias1[NCELLQ * 4];      // (bi,bf,bg,bo) per cell
    float bias2[NCELLQ * 4];
    float outp[NW][SSTR];         // per-warp partial output dots
};

__device__ __forceinline__ float sigf(float x) {
    return 1.0f / (1.0f + __expf(-x));
}
__device__ __forceinline__ float tanh_f(float x) {
    float e = __expf(-2.0f * fabsf(x));
    float t = (1.0f - e) / (1.0f + e);
    return copysignf(t, x);
}
__device__ __forceinline__ ull dup2(float w) {
    ull r; asm("mov.b64 %0, {%1, %1};" : "=l"(r) : "f"(w)); return r;
}
__device__ __forceinline__ void fma2(ull& d, ull a, ull b) {
    asm("fma.rn.f32x2 %0, %1, %2, %0;" : "+l"(d) : "l"(a), "l"(b));
}
__device__ __forceinline__ float2 unpk(ull v) {
    float2 f; asm("mov.b64 {%0, %1}, %2;" : "=f"(f.x), "=f"(f.y) : "l"(v)); return f;
}

__global__ void prep_kernel(const float* __restrict__ in) {
    int stride = gridDim.x * blockDim.x;
    for (int idx = blockIdx.x * blockDim.x + threadIdx.x;
         idx < BPAD * TSTEPS; idx += stride) {
        int b = idx / TSTEPS;
        int t = idx - b * TSTEPS;
        g_xT[t * BPAD + b] = (b < BATCH) ? in[idx] : 0.0f;
    }
}

// GEMM slab: acc over nk k-values using S rows [base..] of Sb and W entries
// Wk[k0..].  8 FFMA2 per k.
__device__ __forceinline__ void slab(ull a[8], const float* __restrict__ Wk,
                                     const float (*Sb)[SSTR], int base,
                                     int k0, int nk, int lane) {
    #pragma unroll 3
    for (int kk = 0; kk < nk; ++kk) {
        ull s2 = dup2(Sb[base + kk][lane]);
        const float* w = Wk + (k0 + kk) * 16;
        ulonglong2 w01 = *reinterpret_cast<const ulonglong2*>(w);
        ulonglong2 w23 = *reinterpret_cast<const ulonglong2*>(w + 4);
        ulonglong2 w45 = *reinterpret_cast<const ulonglong2*>(w + 8);
        ulonglong2 w67 = *reinterpret_cast<const ulonglong2*>(w + 12);
        fma2(a[0], w01.x, s2); fma2(a[1], w01.y, s2);
        fma2(a[2], w23.x, s2); fma2(a[3], w23.y, s2);
        fma2(a[4], w45.x, s2); fma2(a[5], w45.y, s2);
        fma2(a[6], w67.x, s2); fma2(a[7], w67.y, s2);
    }
}

__global__ __launch_bounds__(NTH, 1)
void lstm_kernel(const float* __restrict__ Wih1, const float* __restrict__ Whh1,
                 const float* __restrict__ bih1, const float* __restrict__ bhh1,
                 const float* __restrict__ Wih2, const float* __restrict__ Whh2,
                 const float* __restrict__ bih2, const float* __restrict__ bhh2,
                 const float* __restrict__ Wlin, const float* __restrict__ blin,
                 float* __restrict__ out) {
    extern __shared__ unsigned char smraw[];
    Smem* sm = reinterpret_cast<Smem*>(smraw);
    const int tid  = threadIdx.x;
    const int wid  = tid >> 5;
    const int lane = tid & 31;
    const int b0   = blockIdx.x * NB;
    const int c0   = wid * CPW;           // first cell of this warp

    // ---- one-time init ----
    // W1: [quad][k 0..51][cell*4+gate]; k<51 -> Whh1 col k, k==51 -> Wih1.
    for (int idx = tid; idx < NW * K1 * 16; idx += NTH) {
        int q = idx / (K1 * 16), rem = idx - q * (K1 * 16);
        int k = rem >> 4, j = rem & 15;
        int c = q * CPW + (j >> 2), g4 = j & 3;
        float v = 0.0f;
        if (c < H) {
            int row = g4 * H + c;
            v = (k < H) ? Whh1[row * H + k] : Wih1[row];
        }
        sm->W1[idx] = v;
    }
    // W2: k 0..50 -> Wih2 col k (against h1); k 51..101 -> Whh2 col k-51.
    for (int idx = tid; idx < NW * (2*KH) * 16; idx += NTH) {
        int q = idx / (2*KH * 16), rem = idx - q * (2*KH * 16);
        int k = rem >> 4, j = rem & 15;
        int c = q * CPW + (j >> 2), g4 = j & 3;
        float v = 0.0f;
        if (c < H) {
            int row = g4 * H + c;
            v = (k < H) ? Wih2[row * H + k] : Whh2[row * H + (k - H)];
        }
        sm->W2[idx] = v;
    }
    for (int idx = tid; idx < NCELLQ * 4; idx += NTH) {
        int c = idx >> 2, g4 = idx & 3;
        float v1 = 0.0f, v2 = 0.0f;
        if (c < H) {
            int row = g4 * H + c;
            v1 = bih1[row] + bhh1[row];
            v2 = bih2[row] + bhh2[row];
        }
        sm->bias1[idx] = v1;
        sm->bias2[idx] = v2;
    }
    for (int idx = tid; idx < 2 * SROWS * SSTR; idx += NTH)
        (&sm->Sbuf[0][0][0])[idx] = 0.0f;
    __syncthreads();
    // stage x(0) into Sbuf[0] (parity of t=0)
    if (tid < NB) sm->Sbuf[0][H][tid] = g_xT[b0 + tid];
    __syncthreads();

    // per-warp constants
    const float* Wk1 = sm->W1 + wid * (K1 * 16);
    const float* Wk2 = sm->W2 + wid * (2*KH * 16);
    float wl[CPW];
    #pragma unroll
    for (int j = 0; j < CPW; ++j)
        wl[j] = (c0 + j < H) ? Wlin[c0 + j] : 0.0f;
    const float blin_v = blin[0];
    // row indices for h writes (pad cell -> dummy row 104)
    int r1[CPW], r2[CPW];
    #pragma unroll
    for (int j = 0; j < CPW; ++j) {
        int c = c0 + j;
        r1[j] = (c < H) ? c : 104;
        r2[j] = (c < H) ? 53 + c : 104;
    }

    float c1r[CPW] = {0,0,0,0};
    float c2r[CPW] = {0,0,0,0};

    for (int t = 0; t < NTOT; ++t) {
        const int p = t & 1;
        const float (*Sp)[SSTR] = sm->Sbuf[p];       // prev-state buffer
        float (*Sn)[SSTR]       = sm->Sbuf[1 - p];   // next-state buffer

        // ================= P1: out-reduce / x-stage + GEMM1 + cell1 ========
        if (wid == 0 && lane < NB) {
            if (t > 0 && t < TSTEPS) {               // reduce out(t-1), store
                float acc = blin_v;
                #pragma unroll
                for (int w = 0; w < NW; ++w) acc += sm->outp[w][lane];
                int b = b0 + lane;
                if (b < BATCH) out[b * NTOT + (t - 1)] = acc;
            }
            if (t + 1 < TSTEPS)                      // stage x(t+1) -> Sn[51]
                Sn[H][lane] = g_xT[(t + 1) * BPAD + b0 + lane];
        }

        {   // GEMM1: k = 52 rows of Sp (h1(t-1) + x(t))
            ull a[8];
            #pragma unroll
            for (int j = 0; j < CPW; ++j) {
                ulonglong2 bq = *reinterpret_cast<const ulonglong2*>(
                                    &sm->bias1[(c0 + j) * 4]);
                a[2*j] = bq.x; a[2*j + 1] = bq.y;
            }
            slab(a, Wk1, Sp, 0, 0, K1, lane);
            // cell update layer 1 (registers only), write h1 -> Sn
            #pragma unroll
            for (int j = 0; j < CPW; ++j) {
                float2 if_ = unpk(a[2*j]);
                float2 go  = unpk(a[2*j + 1]);
                float cn = sigf(if_.y) * c1r[j] + sigf(if_.x) * tanh_f(go.x);
                float hn = sigf(go.y) * tanh_f(cn);
                c1r[j] = cn;
                if (lane < NB) Sn[r1[j]][lane] = hn;
            }
        }
        __syncthreads();

        // ================= P2: GEMM2 + cell2 + output partial ==============
        {
            ull a[8];
            #pragma unroll
            for (int j = 0; j < CPW; ++j) {
                ulonglong2 bq = *reinterpret_cast<const ulonglong2*>(
                                    &sm->bias2[(c0 + j) * 4]);
                a[2*j] = bq.x; a[2*j + 1] = bq.y;
            }
            slab(a, Wk2, Sn, 0,  0,  KH, lane);   // h1(t)   rows 0..50 of Sn
            slab(a, Wk2, Sp, 53, KH, KH, lane);   // h2(t-1) rows 53..103 of Sp
            float po = 0.0f;
            #pragma unroll
            for (int j = 0; j < CPW; ++j) {
                float2 if_ = unpk(a[2*j]);
                float2 go  = unpk(a[2*j + 1]);
                float cn = sigf(if_.y) * c2r[j] + sigf(if_.x) * tanh_f(go.x);
                float hn = sigf(go.y) * tanh_f(cn);
                c2r[j] = cn;
                if (lane < NB) Sn[r2[j]][lane] = hn;
                po += wl[j] * hn;
            }
            sm->outp[wid][lane] = po;
        }
        __syncthreads();

        // ================= P3 (future tail only): out -> x(t+1) ============
        if (t >= TSTEPS - 1) {
            if (wid == 0 && lane < NB) {
                float acc = blin_v;
                #pragma unroll
                for (int w = 0; w < NW; ++w) acc += sm->outp[w][lane];
                int b = b0 + lane;
                if (b < BATCH) out[b * NTOT + t] = acc;
                // x(t+1) must live in the buffer read as Sp at step t+1,
                // i.e. Sbuf[(t+1)&1] = Sbuf[1-p]  (this was the R4 bug)
                sm->Sbuf[1 - p][H][lane] = acc;
            }
            __syncthreads();
        }
    }
}

extern "C" void kernel_launch(void* const* d_in, const int* in_sizes, int n_in,
                              void* d_out, int out_size) {
    const float* inputs = (const float*)d_in[0];
    const float* Wih1   = (const float*)d_in[1];
    const float* Whh1   = (const float*)d_in[2];
    const float* bih1   = (const float*)d_in[3];
    const float* bhh1   = (const float*)d_in[4];
    const float* Wih2   = (const float*)d_in[5];
    const float* Whh2   = (const float*)d_in[6];
    const float* bih2   = (const float*)d_in[7];
    const float* bhh2   = (const float*)d_in[8];
    const float* Wlin   = (const float*)d_in[9];
    const float* blin   = (const float*)d_in[10];

    cudaFuncSetAttribute(lstm_kernel,
                         cudaFuncAttributeMaxDynamicSharedMemorySize,
                         (int)sizeof(Smem));

    prep_kernel<<<256, 256>>>(inputs);
    lstm_kernel<<<NBLK, NTH, sizeof(Smem)>>>(Wih1, Whh1, bih1, bhh1,
                                             Wih2, Whh2, bih2, bhh2,
                                             Wlin, blin, (float*)d_out);
}